// round 12
// baseline (speedup 1.0000x reference)
#include <cuda_runtime.h>
#include <math.h>

#define NN 4096
#define EE 65536
#define DD 64

// ---------------- static device scratch ----------------
__device__ int                g_cnt_s[NN];
__device__ int                g_cnt_d[NN];
__device__ int                g_rp_s[NN + 1];
__device__ int                g_rp_d[NN + 1];
__device__ unsigned           g_cs[EE];        // out-edges of n: packed (e<<12)|dst
__device__ unsigned           g_cd[EE];        // in-edges of n:  packed (e<<12)|src
__device__ float              g_agg[NN * DD];
__device__ unsigned long long g_keys[NN];
__device__ unsigned short     g_order[NN];
__device__ float              g_xfinal[NN * DD];
__device__ int                g_rem[NN];
__device__ int                g_rel[NN];
__device__ int                g_K[1];

// XLA EmitFastTanh(with_fma=true): fmuladd Horner, clamp
// +-7.99881172180175781 (clamp value proven no-op on this data by R5 vs R10),
// IEEE divide, |x| < 0.0004 -> passthrough x.
static __device__ __forceinline__ float xla_tanh_fma(float v) {
    float ax = fabsf(v);
    float xc = fminf(fmaxf(v, -7.99881172180175781f), 7.99881172180175781f);
    float x2 = __fmul_rn(xc, xc);
    float p = -2.76076847742355e-16f;
    p = __fmaf_rn(p, x2, 2.00018790482477e-13f);
    p = __fmaf_rn(p, x2, -8.60467152213735e-11f);
    p = __fmaf_rn(p, x2, 5.12229709037114e-08f);
    p = __fmaf_rn(p, x2, 1.48572235717979e-05f);
    p = __fmaf_rn(p, x2, 6.37261928875436e-04f);
    p = __fmaf_rn(p, x2, 4.89352455891786e-03f);
    p = __fmul_rn(p, xc);
    float q = 1.19825839466702e-06f;
    q = __fmaf_rn(q, x2, 1.18534705686654e-04f);
    q = __fmaf_rn(q, x2, 2.26843463243900e-03f);
    q = __fmaf_rn(q, x2, 4.89352518554385e-03f);
    float r = __fdiv_rn(p, q);
    return (ax < 0.0004f) ? v : r;
}

// Eigen row-major general_matrix_vector_product, NEON, faithful shape:
//   inner loop peels 4 packets (ptmp0..ptmp3), k-chunk of 16:
//     lane l of ptmp_j accumulates k = 16*i + 4*j + l   (pmadd = vfmaq_f32)
//   epilogue: padd(padd(t0,t1), padd(t2,t3))
//   predux: vadd(low,high) then vpadd -> halving (l0+l2)+(l1+l3)
static __device__ __forceinline__ float eigen_gemv4_dot(const float* __restrict__ a,
                                                        const float* __restrict__ w) {
    float t0[4] = {0.f, 0.f, 0.f, 0.f};
    float t1[4] = {0.f, 0.f, 0.f, 0.f};
    float t2[4] = {0.f, 0.f, 0.f, 0.f};
    float t3[4] = {0.f, 0.f, 0.f, 0.f};
#pragma unroll
    for (int i = 0; i < DD / 16; i++) {
#pragma unroll
        for (int l = 0; l < 4; l++) {
            t0[l] = __fmaf_rn(a[16 * i + 0 + l],  w[16 * i + 0 + l],  t0[l]);
            t1[l] = __fmaf_rn(a[16 * i + 4 + l],  w[16 * i + 4 + l],  t1[l]);
            t2[l] = __fmaf_rn(a[16 * i + 8 + l],  w[16 * i + 8 + l],  t2[l]);
            t3[l] = __fmaf_rn(a[16 * i + 12 + l], w[16 * i + 12 + l], t3[l]);
        }
    }
    float v[4];
#pragma unroll
    for (int l = 0; l < 4; l++)
        v[l] = __fadd_rn(__fadd_rn(t0[l], t1[l]), __fadd_rn(t2[l], t3[l]));
    return __fadd_rn(__fadd_rn(v[0], v[2]), __fadd_rn(v[1], v[3]));
}

__global__ void k_init() {
    int i = blockIdx.x * blockDim.x + threadIdx.x;
    if (i < NN) { g_cnt_s[i] = 0; g_cnt_d[i] = 0; }
}

__global__ void k_count(const int* __restrict__ ei) {
    int e = blockIdx.x * blockDim.x + threadIdx.x;
    if (e >= EE) return;
    atomicAdd(&g_cnt_s[ei[e]], 1);
    atomicAdd(&g_cnt_d[ei[EE + e]], 1);
}

__global__ void k_scan_deg(int which) {
    __shared__ int a[NN], b2[NN];
    int t = threadIdx.x;
    int* cnt = which ? g_cnt_d : g_cnt_s;
    int* rp  = which ? g_rp_d  : g_rp_s;
    for (int i = t; i < NN; i += 1024) a[i] = cnt[i];
    __syncthreads();
    int* src = a; int* dst = b2;
    for (int st = 1; st < NN; st <<= 1) {
        for (int i = t; i < NN; i += 1024) dst[i] = src[i] + ((i >= st) ? src[i - st] : 0);
        __syncthreads();
        int* tmp = src; src = dst; dst = tmp;
    }
    for (int i = t; i < NN; i += 1024) { rp[i + 1] = src[i]; cnt[i] = 0; }
    if (t == 0) rp[0] = 0;
}

__global__ void k_fill(const int* __restrict__ ei) {
    int e = blockIdx.x * blockDim.x + threadIdx.x;
    if (e >= EE) return;
    int s = ei[e], d = ei[EE + e];
    int ps = g_rp_s[s] + atomicAdd(&g_cnt_s[s], 1);
    g_cs[ps] = ((unsigned)e << 12) | (unsigned)d;
    int pd = g_rp_d[d] + atomicAdd(&g_cnt_d[d], 1);
    g_cd[pd] = ((unsigned)e << 12) | (unsigned)s;
}

// sort each CSR row by edge id (packed key ascending). one thread per row.
__global__ void k_rowsort() {
    int r = blockIdx.x * blockDim.x + threadIdx.x;
    if (r >= 2 * NN) return;
    unsigned* arr; int lo, hi;
    if (r < NN) { arr = g_cs; lo = g_rp_s[r]; hi = g_rp_s[r + 1]; }
    else        { arr = g_cd; lo = g_rp_d[r - NN]; hi = g_rp_d[r - NN + 1]; }
    for (int i = lo + 1; i < hi; i++) {
        unsigned v = arr[i]; int j = i - 1;
        while (j >= lo && arr[j] > v) { arr[j + 1] = arr[j]; j--; }
        arr[j + 1] = v;
    }
}

// agg[n][k]: strict sequential fp32 sum over in-edges of n, ascending edge id
// (XLA CPU scatter expansion = sequential dependent fadd chain).
__global__ void k_agg(const float* __restrict__ x) {
    int n = blockIdx.x, k = threadIdx.x;
    int lo = g_rp_d[n], hi = g_rp_d[n + 1];
    float acc = 0.f;
    for (int i = lo; i < hi; i++) {
        int s = (int)(g_cd[i] & 0xFFFu);
        acc = __fadd_rn(acc, x[s * DD + k]);
    }
    g_agg[n * DD + k] = acc;
}

// z = (agg.w_rel + x.w_root) + b; Eigen 4-packet GEMV dots, FMA tanh.
// 64-bit key: descending score, ties -> ascending node index.
__global__ void k_score(const float* __restrict__ x, const float* __restrict__ w_rel,
                        const float* __restrict__ w_root, const float* __restrict__ b) {
    int n = blockIdx.x * blockDim.x + threadIdx.x;
    if (n >= NN) return;
    float z1 = eigen_gemv4_dot(&g_agg[n * DD], w_rel);
    float z2 = eigen_gemv4_dot(&x[n * DD], w_root);
    float z = __fadd_rn(__fadd_rn(z1, z2), b[0]);
    float s = xla_tanh_fma(z);
    unsigned sb = __float_as_uint(s);
    unsigned m = sb ^ ((sb & 0x80000000u) ? 0xFFFFFFFFu : 0x80000000u); // order map
    g_keys[n] = (((unsigned long long)(~m)) << 32) | (unsigned)n;
}

__global__ void __launch_bounds__(1024, 1) k_sort() {
    __shared__ unsigned long long k[NN];
    int t = threadIdx.x;
    for (int i = t; i < NN; i += 1024) k[i] = g_keys[i];
    __syncthreads();
    for (int size = 2; size <= NN; size <<= 1) {
        for (int stride = size >> 1; stride > 0; stride >>= 1) {
            for (int i = t; i < NN / 2; i += 1024) {
                int lo = 2 * i - (i & (stride - 1));
                int hi = lo + stride;
                bool asc = ((lo & size) == 0);
                unsigned long long a = k[lo], b = k[hi];
                if ((a > b) == asc) { k[lo] = b; k[hi] = a; }
            }
            __syncthreads();
        }
    }
    for (int i = t; i < NN; i += 1024) g_order[i] = (unsigned short)(k[i] & 0xFFFFULL);
}

// Sequential greedy star contraction. Single block; state in smem.
__global__ void __launch_bounds__(1024, 1) k_merge(const float* __restrict__ x) {
    __shared__ unsigned short h[NN];
    __shared__ int            mark[NN];
    __shared__ unsigned char  rem[NN];
    __shared__ unsigned char  cen[NN];
    __shared__ unsigned short ord[NN];
    __shared__ unsigned short uniq[1024];
    __shared__ float          part[256];
    __shared__ int            ucnt;
    int t = threadIdx.x;
    for (int i = t; i < NN; i += 1024) {
        h[i] = (unsigned short)i; mark[i] = -1; rem[i] = 1; cen[i] = 0; ord[i] = g_order[i];
    }
    if (t == 0) ucnt = 0;
    __syncthreads();

    for (int step = 0; step < NN; ++step) {
        int n = ord[step];
        if (!rem[n]) continue;
        int rs = g_rp_s[n], re2 = g_rp_s[n + 1];
        for (int e = rs + t; e < re2; e += 1024) {
            int d = (int)(g_cs[e] & 0xFFFu);
            int r = h[d];
            if (!cen[r]) {
                if (atomicExch(&mark[r], step) != step) {
                    int p = atomicAdd(&ucnt, 1);
                    if (p < 1024) uniq[p] = (unsigned short)r;
                    rem[r] = 0;
                }
            }
        }
        __syncthreads();
        int u = min(ucnt, 1024);
        if (t < 256) {
            int dc = t & 63, g = t >> 6;
            float acc = (g == 0) ? x[n * DD + dc] : 0.f;
            for (int j = g; j < u; j += 4) acc += x[((int)uniq[j]) * DD + dc];
            part[t] = acc;
        } else {
            for (int j = t - 256; j < u; j += 768) h[uniq[j]] = (unsigned short)n;
        }
        __syncthreads();
        if (t < 64)
            g_xfinal[n * DD + t] = part[t] + part[64 + t] + part[128 + t] + part[192 + t];
        if (t == 0) { cen[n] = 1; ucnt = 0; }
        __syncthreads();
    }
    for (int i = t; i < NN; i += 1024) g_rem[i] = rem[i];
}

__global__ void k_scan_rel() {
    __shared__ int a[NN], b2[NN];
    int t = threadIdx.x;
    for (int i = t; i < NN; i += 1024) a[i] = g_rem[i];
    __syncthreads();
    int* src = a; int* dst = b2;
    for (int st = 1; st < NN; st <<= 1) {
        for (int i = t; i < NN; i += 1024) dst[i] = src[i] + ((i >= st) ? src[i - st] : 0);
        __syncthreads();
        int* tmp = src; src = dst; dst = tmp;
    }
    for (int i = t; i < NN; i += 1024) {
        g_rel[i] = src[i] - 1;
        if (i == NN - 1) g_K[0] = src[i];
    }
}

// output (float32): x_pooled[NN*DD] | new_edge_index[2*EE] | batch_pooled[NN] | perm[NN]
__global__ void k_fill_nodes(const int* __restrict__ batch, float* __restrict__ out, int out_size) {
    int n = blockIdx.x, t = threadIdx.x;
    if (!g_rem[n]) return;
    int k = g_rel[n];
    int idx = k * DD + t;
    if (idx < out_size) out[idx] = g_xfinal[n * DD + t];
    if (t == 0) {
        int ob = NN * DD + 2 * EE;
        int op = ob + NN;
        if (ob + k < out_size) out[ob + k] = (float)batch[n];
        if (op + k < out_size) out[op + k] = (float)n;
    }
}

__global__ void k_fill_pad(float* __restrict__ out, int out_size) {
    int j = blockIdx.x, t = threadIdx.x;
    int K = g_K[0];
    if (j < K) return;
    int idx = j * DD + t;
    if (idx < out_size) out[idx] = 0.f;
    if (t == 0) {
        int ob = NN * DD + 2 * EE;
        int op = ob + NN;
        if (ob + j < out_size) out[ob + j] = -1.f;
        if (op + j < out_size) out[op + j] = -1.f;
    }
}

__global__ void k_fill_edges(const int* __restrict__ ei, float* __restrict__ out, int out_size) {
    int e = blockIdx.x * blockDim.x + threadIdx.x;
    if (e >= EE) return;
    int s = ei[e], d = ei[EE + e];
    bool v = g_rem[s] && g_rem[d];
    int oe = NN * DD;
    if (oe + e < out_size)      out[oe + e]      = v ? (float)g_rel[s] : -1.f;
    if (oe + EE + e < out_size) out[oe + EE + e] = v ? (float)g_rel[d] : -1.f;
}

extern "C" void kernel_launch(void* const* d_in, const int* in_sizes, int n_in,
                              void* d_out, int out_size) {
    const float* x      = (const float*)d_in[0];
    const int*   ei     = (const int*)d_in[1];
    const int*   batch  = (const int*)d_in[2];
    const float* w_rel  = (const float*)d_in[3];
    const float* w_root = (const float*)d_in[4];
    const float* b      = (const float*)d_in[5];
    float* out = (float*)d_out;

    k_init<<<(NN + 255) / 256, 256>>>();
    k_count<<<EE / 256, 256>>>(ei);
    k_scan_deg<<<1, 1024>>>(0);
    k_scan_deg<<<1, 1024>>>(1);
    k_fill<<<EE / 256, 256>>>(ei);
    k_rowsort<<<(2 * NN + 255) / 256, 256>>>();
    k_agg<<<NN, DD>>>(x);
    k_score<<<(NN + 255) / 256, 256>>>(x, w_rel, w_root, b);
    k_sort<<<1, 1024>>>();
    k_merge<<<1, 1024>>>(x);
    k_scan_rel<<<1, 1024>>>();
    k_fill_nodes<<<NN, DD>>>(batch, out, out_size);
    k_fill_pad<<<NN, DD>>>(out, out_size);
    k_fill_edges<<<EE / 256, 256>>>(ei, out, out_size);
}

// round 13
// speedup vs baseline: 1.3489x; 1.3489x over previous
#include <cuda_runtime.h>
#include <math.h>

#define NN 4096
#define EE 65536
#define DD 64

// ---------------- static device scratch ----------------
__device__ int                g_cnt_s[NN];
__device__ int                g_cnt_d[NN];
__device__ int                g_rp_s[NN + 1];
__device__ int                g_rp_d[NN + 1];
__device__ unsigned           g_cs[EE];        // out-edges of n: packed (e<<12)|dst
__device__ unsigned           g_cd[EE];        // in-edges of n:  packed (e<<12)|src
__device__ float              g_agg[NN * DD];
__device__ unsigned long long g_keys[NN];
__device__ unsigned short     g_order[NN];
__device__ float              g_xfinal[NN * DD];
__device__ int                g_rem[NN];
__device__ int                g_rel[NN];
__device__ int                g_K[1];

// ============ FROZEN SCORE PATH (bit-exact vs reference; DO NOT TOUCH) ======
// XLA EmitFastTanh(with_fma=true): fmuladd Horner, clamp +-7.99881172180175781
static __device__ __forceinline__ float xla_tanh_fma(float v) {
    float ax = fabsf(v);
    float xc = fminf(fmaxf(v, -7.99881172180175781f), 7.99881172180175781f);
    float x2 = __fmul_rn(xc, xc);
    float p = -2.76076847742355e-16f;
    p = __fmaf_rn(p, x2, 2.00018790482477e-13f);
    p = __fmaf_rn(p, x2, -8.60467152213735e-11f);
    p = __fmaf_rn(p, x2, 5.12229709037114e-08f);
    p = __fmaf_rn(p, x2, 1.48572235717979e-05f);
    p = __fmaf_rn(p, x2, 6.37261928875436e-04f);
    p = __fmaf_rn(p, x2, 4.89352455891786e-03f);
    p = __fmul_rn(p, xc);
    float q = 1.19825839466702e-06f;
    q = __fmaf_rn(q, x2, 1.18534705686654e-04f);
    q = __fmaf_rn(q, x2, 2.26843463243900e-03f);
    q = __fmaf_rn(q, x2, 4.89352518554385e-03f);
    float r = __fdiv_rn(p, q);
    return (ax < 0.0004f) ? v : r;
}

// Eigen row-major general_matrix_vector_product, NEON faithful shape:
// 4 packets, k-chunk 16; epilogue padd(padd(t0,t1),padd(t2,t3)); halving predux.
static __device__ __forceinline__ float eigen_gemv4_dot(const float* __restrict__ a,
                                                        const float* __restrict__ w) {
    float t0[4] = {0.f, 0.f, 0.f, 0.f};
    float t1[4] = {0.f, 0.f, 0.f, 0.f};
    float t2[4] = {0.f, 0.f, 0.f, 0.f};
    float t3[4] = {0.f, 0.f, 0.f, 0.f};
#pragma unroll
    for (int i = 0; i < DD / 16; i++) {
#pragma unroll
        for (int l = 0; l < 4; l++) {
            t0[l] = __fmaf_rn(a[16 * i + 0 + l],  w[16 * i + 0 + l],  t0[l]);
            t1[l] = __fmaf_rn(a[16 * i + 4 + l],  w[16 * i + 4 + l],  t1[l]);
            t2[l] = __fmaf_rn(a[16 * i + 8 + l],  w[16 * i + 8 + l],  t2[l]);
            t3[l] = __fmaf_rn(a[16 * i + 12 + l], w[16 * i + 12 + l], t3[l]);
        }
    }
    float v[4];
#pragma unroll
    for (int l = 0; l < 4; l++)
        v[l] = __fadd_rn(__fadd_rn(t0[l], t1[l]), __fadd_rn(t2[l], t3[l]));
    return __fadd_rn(__fadd_rn(v[0], v[2]), __fadd_rn(v[1], v[3]));
}
// ============================================================================

__global__ void k_init() {
    int i = blockIdx.x * blockDim.x + threadIdx.x;
    if (i < NN) { g_cnt_s[i] = 0; g_cnt_d[i] = 0; }
}

__global__ void k_count(const int* __restrict__ ei) {
    int e = blockIdx.x * blockDim.x + threadIdx.x;
    if (e >= EE) return;
    atomicAdd(&g_cnt_s[ei[e]], 1);
    atomicAdd(&g_cnt_d[ei[EE + e]], 1);
}

// both prefix scans in one launch
__global__ void k_scan_deg2() {
    __shared__ int a[NN], b2[NN];
    int t = threadIdx.x;
    for (int w = 0; w < 2; w++) {
        int* cnt = w ? g_cnt_d : g_cnt_s;
        int* rp  = w ? g_rp_d  : g_rp_s;
        for (int i = t; i < NN; i += 1024) a[i] = cnt[i];
        __syncthreads();
        int* src = a; int* dst = b2;
        for (int st = 1; st < NN; st <<= 1) {
            for (int i = t; i < NN; i += 1024) dst[i] = src[i] + ((i >= st) ? src[i - st] : 0);
            __syncthreads();
            int* tmp = src; src = dst; dst = tmp;
        }
        for (int i = t; i < NN; i += 1024) { rp[i + 1] = src[i]; cnt[i] = 0; }
        if (t == 0) rp[0] = 0;
        __syncthreads();
    }
}

__global__ void k_fill(const int* __restrict__ ei) {
    int e = blockIdx.x * blockDim.x + threadIdx.x;
    if (e >= EE) return;
    int s = ei[e], d = ei[EE + e];
    int ps = g_rp_s[s] + atomicAdd(&g_cnt_s[s], 1);
    g_cs[ps] = ((unsigned)e << 12) | (unsigned)d;
    int pd = g_rp_d[d] + atomicAdd(&g_cnt_d[d], 1);
    g_cd[pd] = ((unsigned)e << 12) | (unsigned)s;
}

// sort ONLY g_cd rows by edge id (feeds the bit-exact agg); local-array sort.
// g_cs needs no order: merge dedupe is set-semantics, combine is reassociable.
__global__ void k_rowsort_cd() {
    int r = blockIdx.x * blockDim.x + threadIdx.x;
    if (r >= NN) return;
    int lo = g_rp_d[r], hi = g_rp_d[r + 1];
    int deg = hi - lo;
    if (deg <= 1) return;
    if (deg <= 64) {
        unsigned buf[64];
        for (int i = 0; i < deg; i++) buf[i] = g_cd[lo + i];
        for (int i = 1; i < deg; i++) {
            unsigned v = buf[i]; int j = i - 1;
            while (j >= 0 && buf[j] > v) { buf[j + 1] = buf[j]; j--; }
            buf[j + 1] = v;
        }
        for (int i = 0; i < deg; i++) g_cd[lo + i] = buf[i];
    } else {  // never in practice; correctness fallback
        for (int i = lo + 1; i < hi; i++) {
            unsigned v = g_cd[i]; int j = i - 1;
            while (j >= lo && g_cd[j] > v) { g_cd[j + 1] = g_cd[j]; j--; }
            g_cd[j + 1] = v;
        }
    }
}

// agg[n][k]: strict sequential fp32 sum over in-edges of n, ascending edge id
__global__ void k_agg(const float* __restrict__ x) {
    int n = blockIdx.x, k = threadIdx.x;
    int lo = g_rp_d[n], hi = g_rp_d[n + 1];
    float acc = 0.f;
    for (int i = lo; i < hi; i++) {
        int s = (int)(g_cd[i] & 0xFFFu);
        acc = __fadd_rn(acc, x[s * DD + k]);
    }
    g_agg[n * DD + k] = acc;
}

__global__ void k_score(const float* __restrict__ x, const float* __restrict__ w_rel,
                        const float* __restrict__ w_root, const float* __restrict__ b) {
    int n = blockIdx.x * blockDim.x + threadIdx.x;
    if (n >= NN) return;
    float z1 = eigen_gemv4_dot(&g_agg[n * DD], w_rel);
    float z2 = eigen_gemv4_dot(&x[n * DD], w_root);
    float z = __fadd_rn(__fadd_rn(z1, z2), b[0]);
    float s = xla_tanh_fma(z);
    unsigned sb = __float_as_uint(s);
    unsigned m = sb ^ ((sb & 0x80000000u) ? 0xFFFFFFFFu : 0x80000000u);
    g_keys[n] = (((unsigned long long)(~m)) << 32) | (unsigned)n;
}

__global__ void __launch_bounds__(1024, 1) k_sort() {
    __shared__ unsigned long long k[NN];
    int t = threadIdx.x;
    for (int i = t; i < NN; i += 1024) k[i] = g_keys[i];
    __syncthreads();
    for (int size = 2; size <= NN; size <<= 1) {
        for (int stride = size >> 1; stride > 0; stride >>= 1) {
            for (int i = t; i < NN / 2; i += 1024) {
                int lo = 2 * i - (i & (stride - 1));
                int hi = lo + stride;
                bool asc = ((lo & size) == 0);
                unsigned long long a = k[lo], b = k[hi];
                if ((a > b) == asc) { k[lo] = b; k[hi] = a; }
            }
            __syncthreads();
        }
    }
    for (int i = t; i < NN; i += 1024) g_order[i] = (unsigned short)(k[i] & 0xFFFFULL);
}

// ---------- merge: smem-resident CSR, 256 threads, 2 barriers/active step ----
// dynamic smem layout (bytes):
#define SM_RP    0                       // int[NN+1]
#define SM_MARK  (SM_RP + 4 * (NN + 1))  // int[NN]
#define SM_UCNT  (SM_MARK + 4 * NN)      // int[2]
#define SM_H     (SM_UCNT + 8)           // u16[NN]
#define SM_ORD   (SM_H + 2 * NN)         // u16[NN]
#define SM_COLS  (SM_ORD + 2 * NN)       // u16[EE]
#define SM_UNIQ  (SM_COLS + 2 * EE)      // u16[256]
#define SM_REM   (SM_UNIQ + 2 * 256)     // u8[NN]
#define SM_CEN   (SM_REM + NN)           // u8[NN]
#define SMEM_MERGE (SM_CEN + NN)

__global__ void __launch_bounds__(256, 1) k_merge(const float* __restrict__ x) {
    extern __shared__ char smx[];
    int*            rp   = (int*)(smx + SM_RP);
    int*            mark = (int*)(smx + SM_MARK);
    int*            ucnt2= (int*)(smx + SM_UCNT);
    unsigned short* h    = (unsigned short*)(smx + SM_H);
    unsigned short* ord  = (unsigned short*)(smx + SM_ORD);
    unsigned short* cols = (unsigned short*)(smx + SM_COLS);
    unsigned short* uniq = (unsigned short*)(smx + SM_UNIQ);
    unsigned char*  rem  = (unsigned char*)(smx + SM_REM);
    unsigned char*  cen  = (unsigned char*)(smx + SM_CEN);

    int t = threadIdx.x;
    for (int i = t; i < NN; i += 256) {
        h[i] = (unsigned short)i; mark[i] = -1; rem[i] = 1; cen[i] = 0; ord[i] = g_order[i];
        rp[i] = g_rp_s[i];
    }
    for (int i = t; i < EE; i += 256) cols[i] = (unsigned short)(g_cs[i] & 0xFFFu);
    if (t == 0) { rp[NN] = g_rp_s[NN]; ucnt2[0] = 0; ucnt2[1] = 0; }
    __syncthreads();

    int apar = 0;  // active-step parity (uniform)
    for (int step = 0; step < NN; ++step) {
        int n = ord[step];
        if (!rem[n]) continue;                 // uniform branch (smem state)
        int slot = apar & 1;
        // ---- phase 1: dedupe non-center reps of dests; zero the other slot
        if (t == 0) ucnt2[slot ^ 1] = 0;
        int rs = rp[n], re2 = rp[n + 1];
        for (int e = rs + t; e < re2; e += 256) {
            int d = cols[e];
            int r = h[d];
            if (!cen[r]) {
                if (atomicExch(&mark[r], step) != step) {
                    int p = atomicAdd(&ucnt2[slot], 1);
                    if (p < 256) uniq[p] = (unsigned short)r;
                    rem[r] = 0;
                }
            }
        }
        __syncthreads();
        int u = min(ucnt2[slot], 256);
        // ---- phase 2: combine (t<64) + relabel (t>=64) + bookkeeping
        if (t < DD) {
            float acc = x[n * DD + t];         // self counted again (torch semantics)
            for (int j = 0; j < u; j++) acc += x[((int)uniq[j]) * DD + t];
            g_xfinal[n * DD + t] = acc;
        } else {
            for (int j = t - DD; j < u; j += 256 - DD) h[uniq[j]] = (unsigned short)n;
            if (t == 255) cen[n] = 1;
        }
        __syncthreads();
        apar ^= 1;
    }
    for (int i = t; i < NN; i += 256) g_rem[i] = rem[i];
}

__global__ void k_scan_rel() {
    __shared__ int a[NN], b2[NN];
    int t = threadIdx.x;
    for (int i = t; i < NN; i += 1024) a[i] = g_rem[i];
    __syncthreads();
    int* src = a; int* dst = b2;
    for (int st = 1; st < NN; st <<= 1) {
        for (int i = t; i < NN; i += 1024) dst[i] = src[i] + ((i >= st) ? src[i - st] : 0);
        __syncthreads();
        int* tmp = src; src = dst; dst = tmp;
    }
    for (int i = t; i < NN; i += 1024) {
        g_rel[i] = src[i] - 1;
        if (i == NN - 1) g_K[0] = src[i];
    }
}

// output (float32): x_pooled[NN*DD] | new_edge_index[2*EE] | batch_pooled[NN] | perm[NN]
__global__ void k_fill_nodes(const int* __restrict__ batch, float* __restrict__ out, int out_size) {
    int n = blockIdx.x, t = threadIdx.x;
    if (!g_rem[n]) return;
    int k = g_rel[n];
    int idx = k * DD + t;
    if (idx < out_size) out[idx] = g_xfinal[n * DD + t];
    if (t == 0) {
        int ob = NN * DD + 2 * EE;
        int op = ob + NN;
        if (ob + k < out_size) out[ob + k] = (float)batch[n];
        if (op + k < out_size) out[op + k] = (float)n;
    }
}

__global__ void k_fill_pad(float* __restrict__ out, int out_size) {
    int j = blockIdx.x, t = threadIdx.x;
    int K = g_K[0];
    if (j < K) return;
    int idx = j * DD + t;
    if (idx < out_size) out[idx] = 0.f;
    if (t == 0) {
        int ob = NN * DD + 2 * EE;
        int op = ob + NN;
        if (ob + j < out_size) out[ob + j] = -1.f;
        if (op + j < out_size) out[op + j] = -1.f;
    }
}

__global__ void k_fill_edges(const int* __restrict__ ei, float* __restrict__ out, int out_size) {
    int e = blockIdx.x * blockDim.x + threadIdx.x;
    if (e >= EE) return;
    int s = ei[e], d = ei[EE + e];
    bool v = g_rem[s] && g_rem[d];
    int oe = NN * DD;
    if (oe + e < out_size)      out[oe + e]      = v ? (float)g_rel[s] : -1.f;
    if (oe + EE + e < out_size) out[oe + EE + e] = v ? (float)g_rel[d] : -1.f;
}

extern "C" void kernel_launch(void* const* d_in, const int* in_sizes, int n_in,
                              void* d_out, int out_size) {
    const float* x      = (const float*)d_in[0];
    const int*   ei     = (const int*)d_in[1];
    const int*   batch  = (const int*)d_in[2];
    const float* w_rel  = (const float*)d_in[3];
    const float* w_root = (const float*)d_in[4];
    const float* b      = (const float*)d_in[5];
    float* out = (float*)d_out;

    cudaFuncSetAttribute(k_merge, cudaFuncAttributeMaxDynamicSharedMemorySize, SMEM_MERGE);

    k_init<<<(NN + 255) / 256, 256>>>();
    k_count<<<EE / 256, 256>>>(ei);
    k_scan_deg2<<<1, 1024>>>();
    k_fill<<<EE / 256, 256>>>(ei);
    k_rowsort_cd<<<(NN + 255) / 256, 256>>>();
    k_agg<<<NN, DD>>>(x);
    k_score<<<(NN + 255) / 256, 256>>>(x, w_rel, w_root, b);
    k_sort<<<1, 1024>>>();
    k_merge<<<1, 256, SMEM_MERGE>>>(x);
    k_scan_rel<<<1, 1024>>>();
    k_fill_nodes<<<NN, DD>>>(batch, out, out_size);
    k_fill_pad<<<NN, DD>>>(out, out_size);
    k_fill_edges<<<EE / 256, 256>>>(ei, out, out_size);
}

// round 14
// speedup vs baseline: 2.8210x; 2.0914x over previous
#include <cuda_runtime.h>
#include <math.h>

#define NN 4096
#define EE 65536
#define DD 64

// ---------------- static device scratch ----------------
__device__ int                g_cnt_s[NN];
__device__ int                g_cnt_d[NN];
__device__ int                g_rp_s[NN + 1];
__device__ int                g_rp_d[NN + 1];
__device__ unsigned           g_cs[EE];        // out-edges of n: packed (e<<12)|dst
__device__ unsigned           g_cd[EE];        // in-edges of n:  packed (e<<12)|src
__device__ float              g_agg[NN * DD];
__device__ unsigned long long g_keys[NN];
__device__ unsigned short     g_order[NN];
__device__ int                g_rem[NN];
__device__ int                g_h[NN];
__device__ int                g_rel[NN];
__device__ int                g_K[1];

// ============ FROZEN SCORE PATH (bit-exact vs reference; DO NOT TOUCH) ======
static __device__ __forceinline__ float xla_tanh_fma(float v) {
    float ax = fabsf(v);
    float xc = fminf(fmaxf(v, -7.99881172180175781f), 7.99881172180175781f);
    float x2 = __fmul_rn(xc, xc);
    float p = -2.76076847742355e-16f;
    p = __fmaf_rn(p, x2, 2.00018790482477e-13f);
    p = __fmaf_rn(p, x2, -8.60467152213735e-11f);
    p = __fmaf_rn(p, x2, 5.12229709037114e-08f);
    p = __fmaf_rn(p, x2, 1.48572235717979e-05f);
    p = __fmaf_rn(p, x2, 6.37261928875436e-04f);
    p = __fmaf_rn(p, x2, 4.89352455891786e-03f);
    p = __fmul_rn(p, xc);
    float q = 1.19825839466702e-06f;
    q = __fmaf_rn(q, x2, 1.18534705686654e-04f);
    q = __fmaf_rn(q, x2, 2.26843463243900e-03f);
    q = __fmaf_rn(q, x2, 4.89352518554385e-03f);
    float r = __fdiv_rn(p, q);
    return (ax < 0.0004f) ? v : r;
}

static __device__ __forceinline__ float eigen_gemv4_dot(const float* __restrict__ a,
                                                        const float* __restrict__ w) {
    float t0[4] = {0.f, 0.f, 0.f, 0.f};
    float t1[4] = {0.f, 0.f, 0.f, 0.f};
    float t2[4] = {0.f, 0.f, 0.f, 0.f};
    float t3[4] = {0.f, 0.f, 0.f, 0.f};
#pragma unroll
    for (int i = 0; i < DD / 16; i++) {
#pragma unroll
        for (int l = 0; l < 4; l++) {
            t0[l] = __fmaf_rn(a[16 * i + 0 + l],  w[16 * i + 0 + l],  t0[l]);
            t1[l] = __fmaf_rn(a[16 * i + 4 + l],  w[16 * i + 4 + l],  t1[l]);
            t2[l] = __fmaf_rn(a[16 * i + 8 + l],  w[16 * i + 8 + l],  t2[l]);
            t3[l] = __fmaf_rn(a[16 * i + 12 + l], w[16 * i + 12 + l], t3[l]);
        }
    }
    float v[4];
#pragma unroll
    for (int l = 0; l < 4; l++)
        v[l] = __fadd_rn(__fadd_rn(t0[l], t1[l]), __fadd_rn(t2[l], t3[l]));
    return __fadd_rn(__fadd_rn(v[0], v[2]), __fadd_rn(v[1], v[3]));
}
// ============================================================================

__global__ void k_init() {
    int i = blockIdx.x * blockDim.x + threadIdx.x;
    if (i < NN) { g_cnt_s[i] = 0; g_cnt_d[i] = 0; }
}

__global__ void k_count(const int* __restrict__ ei) {
    int e = blockIdx.x * blockDim.x + threadIdx.x;
    if (e >= EE) return;
    atomicAdd(&g_cnt_s[ei[e]], 1);
    atomicAdd(&g_cnt_d[ei[EE + e]], 1);
}

__global__ void k_scan_deg2() {
    __shared__ int a[NN], b2[NN];
    int t = threadIdx.x;
    for (int w = 0; w < 2; w++) {
        int* cnt = w ? g_cnt_d : g_cnt_s;
        int* rp  = w ? g_rp_d  : g_rp_s;
        for (int i = t; i < NN; i += 1024) a[i] = cnt[i];
        __syncthreads();
        int* src = a; int* dst = b2;
        for (int st = 1; st < NN; st <<= 1) {
            for (int i = t; i < NN; i += 1024) dst[i] = src[i] + ((i >= st) ? src[i - st] : 0);
            __syncthreads();
            int* tmp = src; src = dst; dst = tmp;
        }
        for (int i = t; i < NN; i += 1024) { rp[i + 1] = src[i]; cnt[i] = 0; }
        if (t == 0) rp[0] = 0;
        __syncthreads();
    }
}

__global__ void k_fill(const int* __restrict__ ei) {
    int e = blockIdx.x * blockDim.x + threadIdx.x;
    if (e >= EE) return;
    int s = ei[e], d = ei[EE + e];
    int ps = g_rp_s[s] + atomicAdd(&g_cnt_s[s], 1);
    g_cs[ps] = ((unsigned)e << 12) | (unsigned)d;
    int pd = g_rp_d[d] + atomicAdd(&g_cnt_d[d], 1);
    g_cd[pd] = ((unsigned)e << 12) | (unsigned)s;
}

// sort ONLY g_cd rows by edge id (feeds the bit-exact agg)
__global__ void k_rowsort_cd() {
    int r = blockIdx.x * blockDim.x + threadIdx.x;
    if (r >= NN) return;
    int lo = g_rp_d[r], hi = g_rp_d[r + 1];
    int deg = hi - lo;
    if (deg <= 1) return;
    if (deg <= 64) {
        unsigned buf[64];
        for (int i = 0; i < deg; i++) buf[i] = g_cd[lo + i];
        for (int i = 1; i < deg; i++) {
            unsigned v = buf[i]; int j = i - 1;
            while (j >= 0 && buf[j] > v) { buf[j + 1] = buf[j]; j--; }
            buf[j + 1] = v;
        }
        for (int i = 0; i < deg; i++) g_cd[lo + i] = buf[i];
    } else {
        for (int i = lo + 1; i < hi; i++) {
            unsigned v = g_cd[i]; int j = i - 1;
            while (j >= lo && g_cd[j] > v) { g_cd[j + 1] = g_cd[j]; j--; }
            g_cd[j + 1] = v;
        }
    }
}

// agg[n][k]: strict sequential fp32 sum over in-edges of n, ascending edge id
__global__ void k_agg(const float* __restrict__ x) {
    int n = blockIdx.x, k = threadIdx.x;
    int lo = g_rp_d[n], hi = g_rp_d[n + 1];
    float acc = 0.f;
    for (int i = lo; i < hi; i++) {
        int s = (int)(g_cd[i] & 0xFFFu);
        acc = __fadd_rn(acc, x[s * DD + k]);
    }
    g_agg[n * DD + k] = acc;
}

__global__ void k_score(const float* __restrict__ x, const float* __restrict__ w_rel,
                        const float* __restrict__ w_root, const float* __restrict__ b) {
    int n = blockIdx.x * blockDim.x + threadIdx.x;
    if (n >= NN) return;
    float z1 = eigen_gemv4_dot(&g_agg[n * DD], w_rel);
    float z2 = eigen_gemv4_dot(&x[n * DD], w_root);
    float z = __fadd_rn(__fadd_rn(z1, z2), b[0]);
    float s = xla_tanh_fma(z);
    unsigned sb = __float_as_uint(s);
    unsigned m = sb ^ ((sb & 0x80000000u) ? 0xFFFFFFFFu : 0x80000000u);
    g_keys[n] = (((unsigned long long)(~m)) << 32) | (unsigned)n;
}

__global__ void __launch_bounds__(1024, 1) k_sort() {
    __shared__ unsigned long long k[NN];
    int t = threadIdx.x;
    for (int i = t; i < NN; i += 1024) k[i] = g_keys[i];
    __syncthreads();
    for (int size = 2; size <= NN; size <<= 1) {
        for (int stride = size >> 1; stride > 0; stride >>= 1) {
            for (int i = t; i < NN / 2; i += 1024) {
                int lo = 2 * i - (i & (stride - 1));
                int hi = lo + stride;
                bool asc = ((lo & size) == 0);
                unsigned long long a = k[lo], b = k[hi];
                if ((a > b) == asc) { k[lo] = b; k[hi] = a; }
            }
            __syncthreads();
        }
    }
    for (int i = t; i < NN; i += 1024) g_order[i] = (unsigned short)(k[i] & 0xFFFFULL);
}

// ---------- merge: single warp, smem CSR, immediate relabel, 1 syncwarp/step
// Discrete state only (no feature math in the loop). Combine reconstructed
// later from h[] by parallel kernels.
// smem layout (bytes), 8-aligned where needed:
#define SM_RP    0                         // int[NN+1]       16388
#define SM_MARK  (SM_RP + 4 * (NN + 1))    // int[NN]         16384
#define SM_COLS  ((SM_MARK + 4 * NN + 7) & ~7)  // u16[EE]    131072 (8-aligned)
#define SM_H     (SM_COLS + 2 * EE)        // u16[NN]
#define SM_ORD   (SM_H + 2 * NN)           // u16[NN]  (bit15 = skip flag)
#define SM_INV   (SM_ORD + 2 * NN)         // u16[NN]
#define SM_CEN   (SM_INV + 2 * NN)         // u8[NN]
#define SM_REM   (SM_CEN + NN)             // u8[NN]
#define SMEM_MERGE (SM_REM + NN)

__global__ void __launch_bounds__(32, 1) k_merge() {
    extern __shared__ char smx[];
    int*            rp   = (int*)(smx + SM_RP);
    int*            mark = (int*)(smx + SM_MARK);
    unsigned short* cols = (unsigned short*)(smx + SM_COLS);
    unsigned short* h    = (unsigned short*)(smx + SM_H);
    unsigned short* ordw = (unsigned short*)(smx + SM_ORD);
    unsigned short* inv  = (unsigned short*)(smx + SM_INV);
    unsigned char*  cen  = (unsigned char*)(smx + SM_CEN);
    unsigned char*  rem  = (unsigned char*)(smx + SM_REM);

    int lane = threadIdx.x;
    for (int i = lane; i < NN; i += 32) {
        h[i] = (unsigned short)i; mark[i] = -1; rem[i] = 1; cen[i] = 0;
        unsigned short o = g_order[i];
        ordw[i] = o; inv[o] = (unsigned short)i;
        rp[i] = g_rp_s[i];
    }
    // cols: vectorized load of g_cs (4 edges per uint4), packed u64 store
    const uint4* cs4 = (const uint4*)g_cs;
    for (int i = lane; i < EE / 4; i += 32) {
        uint4 v = cs4[i];
        unsigned long long pk =
            (unsigned long long)(v.x & 0xFFFu)
          | ((unsigned long long)(v.y & 0xFFFu) << 16)
          | ((unsigned long long)(v.z & 0xFFFu) << 32)
          | ((unsigned long long)(v.w & 0xFFFu) << 48);
        *(unsigned long long*)(cols + 4 * i) = pk;
    }
    if (lane == 0) rp[NN] = g_rp_s[NN];
    __syncwarp();

    int step = 0;
    while (step < NN) {
        // ballot-scan for next active step (flags stable between syncwarps)
        for (;;) {
            int idx = step + lane;
            unsigned short v = (idx < NN) ? ordw[idx] : (unsigned short)0x8000;
            unsigned notf = ~__ballot_sync(0xFFFFFFFF, (v & 0x8000) != 0);
            if (notf) { step += __ffs(notf) - 1; break; }
            step += 32;
            if (step >= NN) break;
        }
        if (step >= NN) break;
        int n = ordw[step] & 0xFFF;
        int rs = rp[n], re2 = rp[n + 1];
        for (int e = rs + lane; e < re2; e += 32) {
            int d = cols[e];
            int r = h[d];
            // raced h[d]==n (d absorbed this step) is safe to skip: d's rep
            // was already marked. genuine self-loop is d==n.
            bool ok = (r == n) ? (d == n) : (cen[r] == 0);
            if (ok && atomicExch(&mark[r], step) != step) {
                h[r] = (unsigned short)n;
                rem[r] = 0;
                ordw[inv[r]] = 0x8000;   // r's own step becomes a skip
            }
        }
        if (lane == 0) cen[n] = 1;
        __syncwarp();
        step++;
    }

    // tail: inclusive prefix scan of rem -> g_rel, total -> g_K; export rem,h
    const int chunk = NN / 32;
    int base = lane * chunk;
    int s = 0;
    for (int i = 0; i < chunk; i++) s += rem[base + i];
    int v = s;
    for (int o = 1; o < 32; o <<= 1) {
        int tv = __shfl_up_sync(0xFFFFFFFF, v, o);
        if (lane >= o) v += tv;
    }
    int run = v - s;
    for (int i = 0; i < chunk; i++) {
        run += rem[base + i];
        g_rel[base + i] = run - 1;
    }
    if (lane == 31) g_K[0] = v;
    for (int i = lane; i < NN; i += 32) { g_rem[i] = rem[i]; g_h[i] = h[i]; }
}

// output (float32): x_pooled[NN*DD] | new_edge_index[2*EE] | batch_pooled[NN] | perm[NN]
// init kept rows with x[c] (+ batch/perm scalars) and pad rows >= K
__global__ void k_fill_out(const float* __restrict__ x, const int* __restrict__ batch,
                           float* __restrict__ out, int out_size) {
    int n = blockIdx.x, t = threadIdx.x;
    int K = g_K[0];
    int ob = NN * DD + 2 * EE;
    int op = ob + NN;
    if (g_rem[n]) {
        int k = g_rel[n];
        int idx = k * DD + t;
        if (idx < out_size) out[idx] = x[n * DD + t];
        if (t == 0) {
            if (ob + k < out_size) out[ob + k] = (float)batch[n];
            if (op + k < out_size) out[op + k] = (float)n;
        }
    }
    if (n >= K) {
        int idx = n * DD + t;
        if (idx < out_size) out[idx] = 0.f;
        if (t == 0) {
            if (ob + n < out_size) out[ob + n] = -1.f;
            if (op + n < out_size) out[op + n] = -1.f;
        }
    }
}

// add absorbed rows into their (kept) absorber's pooled row
__global__ void k_pool_add(const float* __restrict__ x, float* __restrict__ out,
                           int out_size) {
    int r = blockIdx.x, t = threadIdx.x;
    if (g_rem[r]) return;           // not absorbed
    int c = g_h[r];
    if (!g_rem[c]) return;          // absorber not kept (self-loop center)
    int idx = g_rel[c] * DD + t;
    if (idx < out_size) atomicAdd(&out[idx], x[r * DD + t]);
}

__global__ void k_fill_edges(const int* __restrict__ ei, float* __restrict__ out, int out_size) {
    int e = blockIdx.x * blockDim.x + threadIdx.x;
    if (e >= EE) return;
    int s = ei[e], d = ei[EE + e];
    bool v = g_rem[s] && g_rem[d];
    int oe = NN * DD;
    if (oe + e < out_size)      out[oe + e]      = v ? (float)g_rel[s] : -1.f;
    if (oe + EE + e < out_size) out[oe + EE + e] = v ? (float)g_rel[d] : -1.f;
}

extern "C" void kernel_launch(void* const* d_in, const int* in_sizes, int n_in,
                              void* d_out, int out_size) {
    const float* x      = (const float*)d_in[0];
    const int*   ei     = (const int*)d_in[1];
    const int*   batch  = (const int*)d_in[2];
    const float* w_rel  = (const float*)d_in[3];
    const float* w_root = (const float*)d_in[4];
    const float* b      = (const float*)d_in[5];
    float* out = (float*)d_out;

    cudaFuncSetAttribute(k_merge, cudaFuncAttributeMaxDynamicSharedMemorySize, SMEM_MERGE);

    k_init<<<(NN + 255) / 256, 256>>>();
    k_count<<<EE / 256, 256>>>(ei);
    k_scan_deg2<<<1, 1024>>>();
    k_fill<<<EE / 256, 256>>>(ei);
    k_rowsort_cd<<<(NN + 255) / 256, 256>>>();
    k_agg<<<NN, DD>>>(x);
    k_score<<<(NN + 255) / 256, 256>>>(x, w_rel, w_root, b);
    k_sort<<<1, 1024>>>();
    k_merge<<<1, 32, SMEM_MERGE>>>();
    k_fill_out<<<NN, DD>>>(x, batch, out, out_size);
    k_pool_add<<<NN, DD>>>(x, out, out_size);
    k_fill_edges<<<EE / 256, 256>>>(ei, out, out_size);
}

// round 16
// speedup vs baseline: 3.3201x; 1.1770x over previous
#include <cuda_runtime.h>
#include <math.h>

#define NN 4096
#define EE 65536
#define DD 64

// ---------------- static device scratch ----------------
__device__ int                g_cnt_s[NN];
__device__ int                g_cnt_d[NN];
__device__ int                g_rp_s[NN + 1];
__device__ int                g_rp_d[NN + 1];
__device__ unsigned           g_cs[EE];        // out-edges of n: packed (e<<12)|dst
__device__ unsigned           g_cd[EE];        // in-edges of n:  packed (e<<12)|src
__device__ float              g_agg[NN * DD];
__device__ unsigned long long g_keys[NN];
__device__ unsigned short     g_order[NN];
__device__ int                g_rem[NN];
__device__ int                g_h[NN];
__device__ int                g_rel[NN];
__device__ int                g_K[1];

// ============ FROZEN SCORE PATH (bit-exact vs reference; DO NOT TOUCH) ======
static __device__ __forceinline__ float xla_tanh_fma(float v) {
    float ax = fabsf(v);
    float xc = fminf(fmaxf(v, -7.99881172180175781f), 7.99881172180175781f);
    float x2 = __fmul_rn(xc, xc);
    float p = -2.76076847742355e-16f;
    p = __fmaf_rn(p, x2, 2.00018790482477e-13f);
    p = __fmaf_rn(p, x2, -8.60467152213735e-11f);
    p = __fmaf_rn(p, x2, 5.12229709037114e-08f);
    p = __fmaf_rn(p, x2, 1.48572235717979e-05f);
    p = __fmaf_rn(p, x2, 6.37261928875436e-04f);
    p = __fmaf_rn(p, x2, 4.89352455891786e-03f);
    p = __fmul_rn(p, xc);
    float q = 1.19825839466702e-06f;
    q = __fmaf_rn(q, x2, 1.18534705686654e-04f);
    q = __fmaf_rn(q, x2, 2.26843463243900e-03f);
    q = __fmaf_rn(q, x2, 4.89352518554385e-03f);
    float r = __fdiv_rn(p, q);
    return (ax < 0.0004f) ? v : r;
}

static __device__ __forceinline__ float eigen_gemv4_dot(const float* __restrict__ a,
                                                        const float* __restrict__ w) {
    float t0[4] = {0.f, 0.f, 0.f, 0.f};
    float t1[4] = {0.f, 0.f, 0.f, 0.f};
    float t2[4] = {0.f, 0.f, 0.f, 0.f};
    float t3[4] = {0.f, 0.f, 0.f, 0.f};
#pragma unroll
    for (int i = 0; i < DD / 16; i++) {
#pragma unroll
        for (int l = 0; l < 4; l++) {
            t0[l] = __fmaf_rn(a[16 * i + 0 + l],  w[16 * i + 0 + l],  t0[l]);
            t1[l] = __fmaf_rn(a[16 * i + 4 + l],  w[16 * i + 4 + l],  t1[l]);
            t2[l] = __fmaf_rn(a[16 * i + 8 + l],  w[16 * i + 8 + l],  t2[l]);
            t3[l] = __fmaf_rn(a[16 * i + 12 + l], w[16 * i + 12 + l], t3[l]);
        }
    }
    float v[4];
#pragma unroll
    for (int l = 0; l < 4; l++)
        v[l] = __fadd_rn(__fadd_rn(t0[l], t1[l]), __fadd_rn(t2[l], t3[l]));
    return __fadd_rn(__fadd_rn(v[0], v[2]), __fadd_rn(v[1], v[3]));
}
// ============================================================================

__global__ void k_init() {
    int i = blockIdx.x * blockDim.x + threadIdx.x;
    if (i < NN) { g_cnt_s[i] = 0; g_cnt_d[i] = 0; }
}

__global__ void k_count(const int* __restrict__ ei) {
    int e = blockIdx.x * blockDim.x + threadIdx.x;
    if (e >= EE) return;
    atomicAdd(&g_cnt_s[ei[e]], 1);
    atomicAdd(&g_cnt_d[ei[EE + e]], 1);
}

// hierarchical scan: 1024 threads x 4 elems, 3 barriers per array
__global__ void __launch_bounds__(1024, 1) k_scan_deg2() {
    __shared__ int wsum[32];
    int t = threadIdx.x, lane = t & 31, wid = t >> 5;
    for (int pass = 0; pass < 2; pass++) {
        int* cnt = pass ? g_cnt_d : g_cnt_s;
        int* rp  = pass ? g_rp_d  : g_rp_s;
        int base = t * 4;
        int c0 = cnt[base], c1 = cnt[base + 1], c2 = cnt[base + 2], c3 = cnt[base + 3];
        int p1 = c0 + c1, p2 = p1 + c2, p3 = p2 + c3;
        int s = p3, v = s;
        for (int o = 1; o < 32; o <<= 1) {
            int tv = __shfl_up_sync(0xFFFFFFFF, v, o);
            if (lane >= o) v += tv;
        }
        if (lane == 31) wsum[wid] = v;
        __syncthreads();
        if (wid == 0) {
            int vv = wsum[lane];
            for (int o = 1; o < 32; o <<= 1) {
                int tv = __shfl_up_sync(0xFFFFFFFF, vv, o);
                if (lane >= o) vv += tv;
            }
            wsum[lane] = vv;
        }
        __syncthreads();
        int off = (wid ? wsum[wid - 1] : 0) + (v - s);
        rp[base + 1] = off + c0; rp[base + 2] = off + p1;
        rp[base + 3] = off + p2; rp[base + 4] = off + p3;
        cnt[base] = 0; cnt[base + 1] = 0; cnt[base + 2] = 0; cnt[base + 3] = 0;
        if (t == 0) rp[0] = 0;
        __syncthreads();
    }
}

__global__ void k_fill(const int* __restrict__ ei) {
    int e = blockIdx.x * blockDim.x + threadIdx.x;
    if (e >= EE) return;
    int s = ei[e], d = ei[EE + e];
    int ps = g_rp_s[s] + atomicAdd(&g_cnt_s[s], 1);
    g_cs[ps] = ((unsigned)e << 12) | (unsigned)d;
    int pd = g_rp_d[d] + atomicAdd(&g_cnt_d[d], 1);
    g_cd[pd] = ((unsigned)e << 12) | (unsigned)s;
}

// fused: sort in-row by edge id (smem) + strict sequential agg (frozen order)
__global__ void __launch_bounds__(DD, 1) k_sortagg(const float* __restrict__ x) {
    __shared__ unsigned row[256];
    int n = blockIdx.x, t = threadIdx.x;
    int lo = g_rp_d[n];
    int deg = g_rp_d[n + 1] - lo;
    float acc = 0.f;
    if (deg <= 256) {
        for (int i = t; i < deg; i += DD) row[i] = g_cd[lo + i];
        __syncthreads();
        if (t == 0) {
            for (int i = 1; i < deg; i++) {
                unsigned v = row[i]; int j = i - 1;
                while (j >= 0 && row[j] > v) { row[j + 1] = row[j]; j--; }
                row[j + 1] = v;
            }
        }
        __syncthreads();
        for (int i = 0; i < deg; i++)
            acc = __fadd_rn(acc, x[(int)(row[i] & 0xFFFu) * DD + t]);
    } else {  // correctness fallback (never hit for this data)
        if (t == 0) {
            for (int i = lo + 1; i < lo + deg; i++) {
                unsigned v = g_cd[i]; int j = i - 1;
                while (j >= lo && g_cd[j] > v) { g_cd[j + 1] = g_cd[j]; j--; }
                g_cd[j + 1] = v;
            }
        }
        __syncthreads();
        for (int i = 0; i < deg; i++)
            acc = __fadd_rn(acc, x[(int)(g_cd[lo + i] & 0xFFFu) * DD + t]);
    }
    g_agg[n * DD + t] = acc;
}

__global__ void k_score(const float* __restrict__ x, const float* __restrict__ w_rel,
                        const float* __restrict__ w_root, const float* __restrict__ b) {
    int n = blockIdx.x * blockDim.x + threadIdx.x;
    if (n >= NN) return;
    float z1 = eigen_gemv4_dot(&g_agg[n * DD], w_rel);
    float z2 = eigen_gemv4_dot(&x[n * DD], w_root);
    float z = __fadd_rn(__fadd_rn(z1, z2), b[0]);
    float s = xla_tanh_fma(z);
    unsigned sb = __float_as_uint(s);
    unsigned m = sb ^ ((sb & 0x80000000u) ? 0xFFFFFFFFu : 0x80000000u);
    g_keys[n] = (((unsigned long long)(~m)) << 32) | (unsigned)n;
}

__global__ void __launch_bounds__(1024, 1) k_sort() {
    __shared__ unsigned long long k[NN];
    int t = threadIdx.x;
    for (int i = t; i < NN; i += 1024) k[i] = g_keys[i];
    __syncthreads();
    for (int size = 2; size <= NN; size <<= 1) {
        for (int stride = size >> 1; stride > 0; stride >>= 1) {
            for (int i = t; i < NN / 2; i += 1024) {
                int lo = 2 * i - (i & (stride - 1));
                int hi = lo + stride;
                bool asc = ((lo & size) == 0);
                unsigned long long a = k[lo], b = k[hi];
                if ((a > b) == asc) { k[lo] = b; k[hi] = a; }
            }
            __syncthreads();
        }
    }
    for (int i = t; i < NN; i += 1024) g_order[i] = (unsigned short)(k[i] & 0xFFFFULL);
}

// ---------- merge: single warp, packed state word, NO atomics --------------
// w[i]: [11:0] rep, CENB = rep-is-center / i-is-center, ABSB = i absorbed.
// Invariant (labels change once): absorbable(d) <=> w[d]==d. All per-step
// writes idempotent => no dedupe needed (combine is reconstructed outside).
#define CENB 0x10000u
#define ABSB 0x20000u
#define SM_RP    0                                   // int[NN+1]
#define SM_W     (SM_RP + 4 * (NN + 1))              // u32[NN]
#define SM_COLS  ((SM_W + 4 * NN + 7) & ~7)          // u16[EE], 8-ALIGNED (u64 stores)
#define SM_ORD   (SM_COLS + 2 * EE)                  // u16[NN] (bit15 = skip)
#define SM_INV   (SM_ORD + 2 * NN)                   // u16[NN]
#define SMEM_MERGE (SM_INV + 2 * NN)

__global__ void __launch_bounds__(32, 1) k_merge() {
    extern __shared__ char smx[];
    int*            rp   = (int*)(smx + SM_RP);
    unsigned*       w    = (unsigned*)(smx + SM_W);
    unsigned short* cols = (unsigned short*)(smx + SM_COLS);
    unsigned short* ordw = (unsigned short*)(smx + SM_ORD);
    unsigned short* inv  = (unsigned short*)(smx + SM_INV);

    int lane = threadIdx.x;
    for (int i = lane; i < NN; i += 32) {
        w[i] = (unsigned)i;
        unsigned short o = g_order[i];
        ordw[i] = o; inv[o] = (unsigned short)i;
        rp[i] = g_rp_s[i];
    }
    const uint4* cs4 = (const uint4*)g_cs;
    for (int i = lane; i < EE / 4; i += 32) {
        uint4 v = cs4[i];
        unsigned long long pk =
            (unsigned long long)(v.x & 0xFFFu)
          | ((unsigned long long)(v.y & 0xFFFu) << 16)
          | ((unsigned long long)(v.z & 0xFFFu) << 32)
          | ((unsigned long long)(v.w & 0xFFFu) << 48);
        *(unsigned long long*)(cols + 4 * i) = pk;
    }
    if (lane == 0) rp[NN] = g_rp_s[NN];
    __syncwarp();

    int step = 0;
    while (step < NN) {
        int n = -1;
        for (;;) {
            int idx = step + lane;
            unsigned short v = (idx < NN) ? ordw[idx] : (unsigned short)0x8000;
            unsigned act = ~__ballot_sync(0xFFFFFFFF, (v & 0x8000) != 0);
            if (act) {
                int win = __ffs(act) - 1;
                step += win;
                n = __shfl_sync(0xFFFFFFFF, (int)v, win) & 0xFFF;
                break;
            }
            step += 32;
            if (step >= NN) break;
        }
        if (step >= NN) break;
        int rs = rp[n], re2 = rp[n + 1];
        bool selfabs = false;
        for (int e = rs + lane; e < re2; e += 32) {
            int d = cols[e];
            unsigned wd = w[d];
            if (wd == (unsigned)d) {            // never absorbed, not a center
                w[d] = (unsigned)n | CENB | ABSB;
                if (d == n) selfabs = true;
                else        ordw[inv[d]] = 0x8000;  // d's future step -> skip
            }
        }
        unsigned sa = __ballot_sync(0xFFFFFFFF, selfabs);
        if (lane == 0) w[n] = (unsigned)n | CENB | (sa ? ABSB : 0u);
        __syncwarp();
        step++;
    }

    // tail: prefix scan of kept = !(w & ABSB) -> g_rel, g_K; export rem/h
    const int chunk = NN / 32;
    int base = lane * chunk;
    int s = 0;
    for (int i = 0; i < chunk; i++) s += (w[base + i] & ABSB) ? 0 : 1;
    int v = s;
    for (int o = 1; o < 32; o <<= 1) {
        int tv = __shfl_up_sync(0xFFFFFFFF, v, o);
        if (lane >= o) v += tv;
    }
    int run = v - s;
    for (int i = 0; i < chunk; i++) {
        int kept = (w[base + i] & ABSB) ? 0 : 1;
        run += kept;
        g_rel[base + i] = run - 1;
        g_rem[base + i] = kept;
        g_h[base + i] = (int)(w[base + i] & 0xFFFu);
    }
    if (lane == 31) g_K[0] = v;
}

// output (float32): x_pooled[NN*DD] | new_edge_index[2*EE] | batch_pooled[NN] | perm[NN]
__global__ void k_fill_out(const float* __restrict__ x, const int* __restrict__ batch,
                           float* __restrict__ out, int out_size) {
    int n = blockIdx.x, t = threadIdx.x;
    int K = g_K[0];
    int ob = NN * DD + 2 * EE;
    int op = ob + NN;
    if (g_rem[n]) {
        int k = g_rel[n];
        int idx = k * DD + t;
        if (idx < out_size) out[idx] = x[n * DD + t];
        if (t == 0) {
            if (ob + k < out_size) out[ob + k] = (float)batch[n];
            if (op + k < out_size) out[op + k] = (float)n;
        }
    }
    if (n >= K) {
        int idx = n * DD + t;
        if (idx < out_size) out[idx] = 0.f;
        if (t == 0) {
            if (ob + n < out_size) out[ob + n] = -1.f;
            if (op + n < out_size) out[op + n] = -1.f;
        }
    }
}

__global__ void k_pool_add(const float* __restrict__ x, float* __restrict__ out,
                           int out_size) {
    int r = blockIdx.x, t = threadIdx.x;
    if (g_rem[r]) return;           // not absorbed
    int c = g_h[r];
    if (!g_rem[c]) return;          // absorber not kept (self-loop center)
    int idx = g_rel[c] * DD + t;
    if (idx < out_size) atomicAdd(&out[idx], x[r * DD + t]);
}

__global__ void k_fill_edges(const int* __restrict__ ei, float* __restrict__ out, int out_size) {
    int e = blockIdx.x * blockDim.x + threadIdx.x;
    if (e >= EE) return;
    int s = ei[e], d = ei[EE + e];
    bool v = g_rem[s] && g_rem[d];
    int oe = NN * DD;
    if (oe + e < out_size)      out[oe + e]      = v ? (float)g_rel[s] : -1.f;
    if (oe + EE + e < out_size) out[oe + EE + e] = v ? (float)g_rel[d] : -1.f;
}

extern "C" void kernel_launch(void* const* d_in, const int* in_sizes, int n_in,
                              void* d_out, int out_size) {
    const float* x      = (const float*)d_in[0];
    const int*   ei     = (const int*)d_in[1];
    const int*   batch  = (const int*)d_in[2];
    const float* w_rel  = (const float*)d_in[3];
    const float* w_root = (const float*)d_in[4];
    const float* b      = (const float*)d_in[5];
    float* out = (float*)d_out;

    cudaFuncSetAttribute(k_merge, cudaFuncAttributeMaxDynamicSharedMemorySize, SMEM_MERGE);

    k_init<<<(NN + 255) / 256, 256>>>();
    k_count<<<EE / 256, 256>>>(ei);
    k_scan_deg2<<<1, 1024>>>();
    k_fill<<<EE / 256, 256>>>(ei);
    k_sortagg<<<NN, DD>>>(x);
    k_score<<<(NN + 255) / 256, 256>>>(x, w_rel, w_root, b);
    k_sort<<<1, 1024>>>();
    k_merge<<<1, 32, SMEM_MERGE>>>();
    k_fill_out<<<NN, DD>>>(x, batch, out, out_size);
    k_pool_add<<<NN, DD>>>(x, out, out_size);
    k_fill_edges<<<EE / 256, 256>>>(ei, out, out_size);
}